// round 11
// baseline (speedup 1.0000x reference)
#include <cuda_runtime.h>

// Problem constants
#define B        8
#define IN_CH    64
#define OUT_CH   64
#define GROUPS   8
#define FPG      8
#define H        256
#define W        256
#define PLANE    (H * W)
#define REP_DIM  32

#define TILE     64
#define SSTRIDE  72      // padded smem row stride (float4-friendly)
#define SINT     4       // interior column base in S (left halo at col 3)
#define THREADS  256

// ---------------------------------------------------------------------------
// Fused kernel, 2 y-tiles per CTA, double-buffered smem:
//   load S[0](tile0) ; bar ; compute0 ; load S[1](tile1) ; bar ; compute1
// Warps finishing compute0 early start tile1 LDGs immediately (no barrier
// between compute0 and load1 — distinct buffers). grid = 512 = single wave.
// ---------------------------------------------------------------------------
__device__ __forceinline__ int reflect_idx(int i) {
    i = (i < 0) ? -i : i;
    return (i > H - 1) ? (2 * (H - 1) - i) : i;
}

__global__ __launch_bounds__(THREADS, 4)
void dyn_conv_kernel(const float* __restrict__ x,
                     const float* __restrict__ rep,
                     const float* __restrict__ Wm,
                     float* __restrict__ out) {
    const int b = blockIdx.z;
    const int g = blockIdx.y;
    const int ty0 = (blockIdx.x >> 2) * 128;   // y-pair base: 0 or 128
    const int tx  = (blockIdx.x & 3) * TILE;
    const int tid = threadIdx.x;

    __shared__ float S[2][66 * SSTRIDE];   // double-buffered group-sum tile
    __shared__ float k9s[FPG * 9];

    // ---- Dynamic weights: 72 dot-products of length 32 (threads 0..71) ----
    if (tid < FPG * 9) {
        const int f = (g * FPG) * 9 + tid;
        const float4* r4 = (const float4*)(rep + b * REP_DIM);
        const float4* w4 = (const float4*)(Wm + (size_t)f * REP_DIM);
        float s = 0.f;
#pragma unroll
        for (int i = 0; i < REP_DIM / 4; i++) {
            float4 rv = __ldg(&r4[i]);
            float4 wv = __ldg(&w4[i]);
            s = fmaf(rv.x, wv.x, s);
            s = fmaf(rv.y, wv.y, s);
            s = fmaf(rv.z, wv.z, s);
            s = fmaf(rv.w, wv.w, s);
        }
        k9s[tid] = (s > 0.f) ? s : 0.1f * s;
    }

    const float* xbase = x + ((size_t)(b * IN_CH + g * FPG)) * PLANE;

    // Compute-phase thread coords (fixed across both tiles)
    const int xq    = tid & 15;          // 0..15 -> cols xq*4..xq*4+3
    const int strip = (tid >> 4) & 3;    // 0..3  -> rows strip*16..+15
    const int chq   = tid >> 6;          // 0..3  -> channels chq*2, chq*2+1
    const int lx0   = xq * 4;
    const int ys    = strip * 16;
    const int co0   = chq * 2;

    float kr[18];
    bool kr_loaded = false;

#pragma unroll
    for (int t = 0; t < 2; t++) {
        const int ty = ty0 + t * TILE;
        float* Sb = S[t];

        // ---- Interior: 66 rows x 16 float4 (1056 tasks: 4 full + tail) ----
#pragma unroll
        for (int it = 0; it < 4; it++) {
            int i = tid + it * THREADS;
            int row = i >> 4;
            int c4  = i & 15;
            int gy = reflect_idx(ty + row - 1);
            const float* p = xbase + gy * W + tx + c4 * 4;
            float4 s = make_float4(0.f, 0.f, 0.f, 0.f);
#pragma unroll
            for (int c = 0; c < FPG; c++) {
                float4 v = *(const float4*)(p + c * PLANE);
                s.x += v.x; s.y += v.y; s.z += v.z; s.w += v.w;
            }
            *(float4*)&Sb[row * SSTRIDE + SINT + c4 * 4] = s;
        }
        if (tid < 32) {
            int i = 1024 + tid;
            int row = i >> 4;
            int c4  = i & 15;
            int gy = reflect_idx(ty + row - 1);
            const float* p = xbase + gy * W + tx + c4 * 4;
            float4 s = make_float4(0.f, 0.f, 0.f, 0.f);
#pragma unroll
            for (int c = 0; c < FPG; c++) {
                float4 v = *(const float4*)(p + c * PLANE);
                s.x += v.x; s.y += v.y; s.z += v.z; s.w += v.w;
            }
            *(float4*)&Sb[row * SSTRIDE + SINT + c4 * 4] = s;
        }

        // ---- Halo columns: 66 rows x 2 sides ----
        if (tid < 132) {
            int row  = tid >> 1;
            int side = tid & 1;
            int gy = reflect_idx(ty + row - 1);
            int gx = side ? reflect_idx(tx + 64) : reflect_idx(tx - 1);
            const float* p = xbase + gy * W + gx;
            float s = 0.f;
#pragma unroll
            for (int c = 0; c < FPG; c++) s += p[c * PLANE];
            Sb[row * SSTRIDE + (side ? (SINT + 64) : (SINT - 1))] = s;
        }
        __syncthreads();

        if (!kr_loaded) {
            kr_loaded = true;
#pragma unroll
            for (int c = 0; c < 2; c++)
#pragma unroll
                for (int tt = 0; tt < 9; tt++)
                    kr[c * 9 + tt] = k9s[(co0 + c) * 9 + tt];
        }

        // ---- Compute: 4 cols x 16 rows x 2 channels per thread ----
        float w0[6], w1[6], w2[6];
        {
            const float* Sp = &Sb[ys * SSTRIDE + lx0 + 3];
#pragma unroll
            for (int j = 0; j < 6; j++) w0[j] = Sp[j];
            Sp += SSTRIDE;
#pragma unroll
            for (int j = 0; j < 6; j++) w1[j] = Sp[j];
        }

        float* op = out + ((size_t)(b * OUT_CH + g * FPG + co0)) * PLANE
                        + (ty + ys) * W + tx + lx0;

#pragma unroll 4
        for (int y = 0; y < 16; y++) {
            const float* Sp = &Sb[(ys + y + 2) * SSTRIDE + lx0 + 3];
#pragma unroll
            for (int j = 0; j < 6; j++) w2[j] = Sp[j];

#pragma unroll
            for (int c = 0; c < 2; c++) {
                const float* k = &kr[c * 9];
                float4 r;
                r.x = k[0] * w0[0]; r.y = k[0] * w0[1];
                r.z = k[0] * w0[2]; r.w = k[0] * w0[3];
                r.x = fmaf(k[1], w0[1], r.x); r.y = fmaf(k[1], w0[2], r.y);
                r.z = fmaf(k[1], w0[3], r.z); r.w = fmaf(k[1], w0[4], r.w);
                r.x = fmaf(k[2], w0[2], r.x); r.y = fmaf(k[2], w0[3], r.y);
                r.z = fmaf(k[2], w0[4], r.z); r.w = fmaf(k[2], w0[5], r.w);
                r.x = fmaf(k[3], w1[0], r.x); r.y = fmaf(k[3], w1[1], r.y);
                r.z = fmaf(k[3], w1[2], r.z); r.w = fmaf(k[3], w1[3], r.w);
                r.x = fmaf(k[4], w1[1], r.x); r.y = fmaf(k[4], w1[2], r.y);
                r.z = fmaf(k[4], w1[3], r.z); r.w = fmaf(k[4], w1[4], r.w);
                r.x = fmaf(k[5], w1[2], r.x); r.y = fmaf(k[5], w1[3], r.y);
                r.z = fmaf(k[5], w1[4], r.z); r.w = fmaf(k[5], w1[5], r.w);
                r.x = fmaf(k[6], w2[0], r.x); r.y = fmaf(k[6], w2[1], r.y);
                r.z = fmaf(k[6], w2[2], r.z); r.w = fmaf(k[6], w2[3], r.w);
                r.x = fmaf(k[7], w2[1], r.x); r.y = fmaf(k[7], w2[2], r.y);
                r.z = fmaf(k[7], w2[3], r.z); r.w = fmaf(k[7], w2[4], r.w);
                r.x = fmaf(k[8], w2[2], r.x); r.y = fmaf(k[8], w2[3], r.y);
                r.z = fmaf(k[8], w2[4], r.z); r.w = fmaf(k[8], w2[5], r.w);
                __stcs((float4*)(op + c * PLANE), r);
            }
            op += W;
#pragma unroll
            for (int j = 0; j < 6; j++) { w0[j] = w1[j]; w1[j] = w2[j]; }
        }

        // No barrier here: next loop iteration writes the OTHER smem buffer;
        // the __syncthreads() before its compute phase is the only sync needed.
    }
}

// ---------------------------------------------------------------------------
// Launch
// ---------------------------------------------------------------------------
extern "C" void kernel_launch(void* const* d_in, const int* in_sizes, int n_in,
                              void* d_out, int out_size) {
    const float* x   = (const float*)d_in[0];   // [8, 64, 256, 256]
    const float* rep = (const float*)d_in[1];   // [8, 32]
    const float* Wm  = (const float*)d_in[2];   // [576, 32]
    float* out = (float*)d_out;                 // [8, 64, 256, 256]

    (void)in_sizes; (void)n_in; (void)out_size;

    dim3 grid(8, GROUPS, B);   // 4 x-tiles x 2 y-pairs, 8 groups, 8 batches
    dyn_conv_kernel<<<grid, THREADS>>>(x, rep, Wm, out);
}

// round 13
// speedup vs baseline: 1.0286x; 1.0286x over previous
#include <cuda_runtime.h>

// Problem constants
#define B        8
#define IN_CH    64
#define OUT_CH   64
#define GROUPS   8
#define FPG      8
#define H        256
#define W        256
#define PLANE    (H * W)
#define REP_DIM  32

#define TILE     64
#define SSTRIDE  72      // padded smem row stride (float4-friendly)
#define SINT     4       // interior column base in S (left halo at col 3)
#define THREADS  256

// ---------------------------------------------------------------------------
// Fused kernel (R6 frame): single 64x64 tile per CTA, grid (16, 8, 8).
//  - threads 0..71 compute the (b,g) dynamic weights (leaky_relu(rep.W))
//  - interior S built pair-split: lanes (l, l^16) each sum 4 channels,
//    combined with a shfl_xor butterfly; lane<16 stores. One S-row per warp.
//  - compute: thread = 4 cols x 16 rows x 2 channels, STG.128 streaming.
// ---------------------------------------------------------------------------
__device__ __forceinline__ int reflect_idx(int i) {
    i = (i < 0) ? -i : i;
    return (i > H - 1) ? (2 * (H - 1) - i) : i;
}

__global__ __launch_bounds__(THREADS, 4)
void dyn_conv_kernel(const float* __restrict__ x,
                     const float* __restrict__ rep,
                     const float* __restrict__ Wm,
                     float* __restrict__ out) {
    const int b = blockIdx.z;
    const int g = blockIdx.y;
    const int ty = (blockIdx.x >> 2) * TILE;
    const int tx = (blockIdx.x & 3) * TILE;
    const int tid = threadIdx.x;
    const int lane = tid & 31;

    __shared__ float S[66 * SSTRIDE];    // group-sum tile + halo
    __shared__ float k9s[FPG * 9];

    // ---- Dynamic weights: 72 dot-products of length 32 (threads 0..71) ----
    if (tid < FPG * 9) {
        const int f = (g * FPG) * 9 + tid;
        const float4* r4 = (const float4*)(rep + b * REP_DIM);
        const float4* w4 = (const float4*)(Wm + (size_t)f * REP_DIM);
        float s = 0.f;
#pragma unroll
        for (int i = 0; i < REP_DIM / 4; i++) {
            float4 rv = __ldg(&r4[i]);
            float4 wv = __ldg(&w4[i]);
            s = fmaf(rv.x, wv.x, s);
            s = fmaf(rv.y, wv.y, s);
            s = fmaf(rv.z, wv.z, s);
            s = fmaf(rv.w, wv.w, s);
        }
        k9s[tid] = (s > 0.f) ? s : 0.1f * s;
    }

    const float* xbase = x + ((size_t)(b * IN_CH + g * FPG)) * PLANE;

    // Per-lane channel half for the pair-split: lanes 0-15 -> ch 0-3,
    // lanes 16-31 -> ch 4-7; column c4 = lane & 15.
    const int c4    = lane & 15;
    const int choff = (lane >> 4) * 4;   // 0 or 4

    // ---- Interior: 66 rows, one row per warp per iteration.
    //      subtask s = tid + it*256 ; row = s >> 5 (constant within a warp).
#pragma unroll
    for (int it = 0; it < 8; it++) {
        int row = (tid + it * THREADS) >> 5;
        int gy = reflect_idx(ty + row - 1);
        const float* p = xbase + (size_t)(choff) * PLANE + gy * W + tx + c4 * 4;
        float4 s = make_float4(0.f, 0.f, 0.f, 0.f);
#pragma unroll
        for (int c = 0; c < 4; c++) {
            float4 v = *(const float4*)(p + c * PLANE);
            s.x += v.x; s.y += v.y; s.z += v.z; s.w += v.w;
        }
        // Butterfly: combine the two channel-halves across lane^16.
        s.x += __shfl_xor_sync(0xffffffffu, s.x, 16);
        s.y += __shfl_xor_sync(0xffffffffu, s.y, 16);
        s.z += __shfl_xor_sync(0xffffffffu, s.z, 16);
        s.w += __shfl_xor_sync(0xffffffffu, s.w, 16);
        if (lane < 16) {
            *(float4*)&S[row * SSTRIDE + SINT + c4 * 4] = s;
        }
    }
    // Tail rows 64, 65 (2 warps: tid < 64)
    if (tid < 64) {
        int row = (2048 + tid) >> 5;
        int gy = reflect_idx(ty + row - 1);
        const float* p = xbase + (size_t)(choff) * PLANE + gy * W + tx + c4 * 4;
        float4 s = make_float4(0.f, 0.f, 0.f, 0.f);
#pragma unroll
        for (int c = 0; c < 4; c++) {
            float4 v = *(const float4*)(p + c * PLANE);
            s.x += v.x; s.y += v.y; s.z += v.z; s.w += v.w;
        }
        s.x += __shfl_xor_sync(0xffffffffu, s.x, 16);
        s.y += __shfl_xor_sync(0xffffffffu, s.y, 16);
        s.z += __shfl_xor_sync(0xffffffffu, s.z, 16);
        s.w += __shfl_xor_sync(0xffffffffu, s.w, 16);
        if (lane < 16) {
            *(float4*)&S[row * SSTRIDE + SINT + c4 * 4] = s;
        }
    }

    // ---- Halo columns: 66 rows x 2 sides, scalar 8-channel sums ----
    if (tid < 132) {
        int row  = tid >> 1;
        int side = tid & 1;
        int gy = reflect_idx(ty + row - 1);
        int gx = side ? reflect_idx(tx + 64) : reflect_idx(tx - 1);
        const float* p = xbase + gy * W + gx;
        float s = 0.f;
#pragma unroll
        for (int c = 0; c < FPG; c++) s += p[c * PLANE];
        S[row * SSTRIDE + (side ? (SINT + 64) : (SINT - 1))] = s;
    }
    __syncthreads();

    // ---- Compute: thread = (xq, strip, chq) -> 4 cols, 16 rows, 2 channels
    const int xq    = tid & 15;
    const int strip = (tid >> 4) & 3;
    const int chq   = tid >> 6;
    const int lx0   = xq * 4;
    const int y0    = strip * 16;
    const int co0   = chq * 2;

    float kr[18];
#pragma unroll
    for (int c = 0; c < 2; c++)
#pragma unroll
        for (int t = 0; t < 9; t++)
            kr[c * 9 + t] = k9s[(co0 + c) * 9 + t];

    float w0[6], w1[6], w2[6];
    {
        const float* Sp = &S[y0 * SSTRIDE + lx0 + 3];
#pragma unroll
        for (int j = 0; j < 6; j++) w0[j] = Sp[j];
        Sp += SSTRIDE;
#pragma unroll
        for (int j = 0; j < 6; j++) w1[j] = Sp[j];
    }

    float* op = out + ((size_t)(b * OUT_CH + g * FPG + co0)) * PLANE
                    + (ty + y0) * W + tx + lx0;

#pragma unroll 4
    for (int y = 0; y < 16; y++) {
        const float* Sp = &S[(y0 + y + 2) * SSTRIDE + lx0 + 3];
#pragma unroll
        for (int j = 0; j < 6; j++) w2[j] = Sp[j];

#pragma unroll
        for (int c = 0; c < 2; c++) {
            const float* k = &kr[c * 9];
            float4 r;
            r.x = k[0] * w0[0]; r.y = k[0] * w0[1];
            r.z = k[0] * w0[2]; r.w = k[0] * w0[3];
            r.x = fmaf(k[1], w0[1], r.x); r.y = fmaf(k[1], w0[2], r.y);
            r.z = fmaf(k[1], w0[3], r.z); r.w = fmaf(k[1], w0[4], r.w);
            r.x = fmaf(k[2], w0[2], r.x); r.y = fmaf(k[2], w0[3], r.y);
            r.z = fmaf(k[2], w0[4], r.z); r.w = fmaf(k[2], w0[5], r.w);
            r.x = fmaf(k[3], w1[0], r.x); r.y = fmaf(k[3], w1[1], r.y);
            r.z = fmaf(k[3], w1[2], r.z); r.w = fmaf(k[3], w1[3], r.w);
            r.x = fmaf(k[4], w1[1], r.x); r.y = fmaf(k[4], w1[2], r.y);
            r.z = fmaf(k[4], w1[3], r.z); r.w = fmaf(k[4], w1[4], r.w);
            r.x = fmaf(k[5], w1[2], r.x); r.y = fmaf(k[5], w1[3], r.y);
            r.z = fmaf(k[5], w1[4], r.z); r.w = fmaf(k[5], w1[5], r.w);
            r.x = fmaf(k[6], w2[0], r.x); r.y = fmaf(k[6], w2[1], r.y);
            r.z = fmaf(k[6], w2[2], r.z); r.w = fmaf(k[6], w2[3], r.w);
            r.x = fmaf(k[7], w2[1], r.x); r.y = fmaf(k[7], w2[2], r.y);
            r.z = fmaf(k[7], w2[3], r.z); r.w = fmaf(k[7], w2[4], r.w);
            r.x = fmaf(k[8], w2[2], r.x); r.y = fmaf(k[8], w2[3], r.y);
            r.z = fmaf(k[8], w2[4], r.z); r.w = fmaf(k[8], w2[5], r.w);
            __stcs((float4*)(op + c * PLANE), r);
        }
        op += W;
#pragma unroll
        for (int j = 0; j < 6; j++) { w0[j] = w1[j]; w1[j] = w2[j]; }
    }
}

// ---------------------------------------------------------------------------
// Launch
// ---------------------------------------------------------------------------
extern "C" void kernel_launch(void* const* d_in, const int* in_sizes, int n_in,
                              void* d_out, int out_size) {
    const float* x   = (const float*)d_in[0];   // [8, 64, 256, 256]
    const float* rep = (const float*)d_in[1];   // [8, 32]
    const float* Wm  = (const float*)d_in[2];   // [576, 32]
    float* out = (float*)d_out;                 // [8, 64, 256, 256]

    (void)in_sizes; (void)n_in; (void)out_size;

    dim3 grid(16, GROUPS, B);   // single 64x64 tile per CTA (R6 frame)
    dyn_conv_kernel<<<grid, THREADS>>>(x, rep, Wm, out);
}